// round 14
// baseline (speedup 1.0000x reference)
#include <cuda_runtime.h>
#include <cstdint>
#include <cstddef>

// RNN_49297634623576: out = fc_w @ tanh(w_ih @ x[:,27,:] + b_ih + b_hh) + fc_b
// hx == 0 => w_hh unused.
//
// R14 model (fits R8, R10-R13 quantitatively): the CONST PORT supplies only
// ~3.5 B/cyc/SM (LDC or LDCU alike). R12/13: 28 warps x 3.5KB = 98KB ->
// 26.5k cyc == measured 14.7us. R10: 101KB -> 31k ✓. R8: ~33k ✓. fma floor
// is 8.4k cyc (4.7us). Fix: split the weight stream across two ports —
// even j via LDCU (immediate addresses), odd j via broadcast LDS.128 from
// shared. Each port carries ~half: const 49KB/SM ~13k cyc, L1 ~12k wf,
// fma 8.4k -> predicted ~13k cyc (~7.5us kernel).
// Kept from R12/13: warp-split halves, 1024 CTAs, 7 CTAs/SM, 1 memcpy node.

#define NB   65536
#define NIN  28
#define NHID 64
#define NOUT 10
#define TPB  128   // 4 warps: (half, rowgroup); 64 rows/CTA -> 1024 CTAs

typedef unsigned long long u64;

__constant__ u64 c_w64[NHID * NIN / 2];  // raw w_ih: [j][p] = {w[j][2p], w[j][2p+1]}

__device__ __forceinline__ u64 pk2(float a, float b) {
    u64 r; asm("mov.b64 %0,{%1,%2};" : "=l"(r) : "f"(a), "f"(b)); return r;
}
__device__ __forceinline__ void upk2(u64 v, float& a, float& b) {
    asm("mov.b64 {%0,%1},%2;" : "=f"(a), "=f"(b) : "l"(v));
}
__device__ __forceinline__ u64 ffma2(u64 a, u64 b, u64 c) {
    u64 d; asm("fma.rn.f32x2 %0,%1,%2,%3;" : "=l"(d) : "l"(a), "l"(b), "l"(c)); return d;
}
__device__ __forceinline__ u64 fadd2(u64 a, u64 b) {
    u64 d; asm("add.rn.f32x2 %0,%1,%2;" : "=l"(d) : "l"(a), "l"(b)); return d;
}
__device__ __forceinline__ float hsum2(u64 v) {
    float a, b; upk2(v, a, b); return a + b;
}

// tanh(x) = 1 - 2*rcp(exp2(x*2log2e)+1); ~1e-6 accurate.
__device__ __forceinline__ float tanh_fast(float x) {
    const float LOG2E_X2 = 2.8853900817779268f;
    float e, r;
    asm("ex2.approx.ftz.f32 %0, %1;" : "=f"(e) : "f"(x * LOG2E_X2));
    asm("rcp.approx.ftz.f32 %0, %1;" : "=f"(r) : "f"(e + 1.0f));
    return fmaf(-2.0f, r, 1.0f);
}

// One half's work: 32 hidden units [JBASE, JBASE+32), 2 j per iteration.
// Even j weights: LDCU with immediate addresses (const port).
// Odd  j weights: 7 broadcast LDS.128 from shared (smem port).
template <int JBASE>
__device__ __forceinline__ void half_work(const u64 (&in)[NIN / 2],
                                          const u64* s_bp,
                                          const u64 (*s_wodd)[16],
                                          const u64 (*s_fck)[6],
                                          u64 (&oa)[NOUT / 2])
{
#pragma unroll
    for (int jj = 0; jj < 32; jj += 2) {
        const int j0 = JBASE + jj;       // even -> const port
        const int j1 = j0 + 1;           // odd  -> smem port

        // Odd-j weight row via broadcast LDS.128.
        const ulonglong2* rw = reinterpret_cast<const ulonglong2*>(&s_wodd[j1 >> 1][0]);
        ulonglong2 W[7];
#pragma unroll
        for (int p = 0; p < 7; p++) W[p] = rw[p];

        // Two independent layer-1 chains, biases seeded from smem broadcast.
        u64 a0 = s_bp[j0];
        u64 a1 = s_bp[j1];
#pragma unroll
        for (int p = 0; p < 7; p++) {
            a0 = ffma2(c_w64[j0 * (NIN / 2) + 2 * p],     in[2 * p],     a0);
            a1 = ffma2(W[p].x,                            in[2 * p],     a1);
            a0 = ffma2(c_w64[j0 * (NIN / 2) + 2 * p + 1], in[2 * p + 1], a0);
            a1 = ffma2(W[p].y,                            in[2 * p + 1], a1);
        }

        // Two parallel tanh chains.
        float h0 = tanh_fast(hsum2(a0));
        float h1 = tanh_fast(hsum2(a1));
        u64 hp0 = pk2(h0, h0);
        u64 hp1 = pk2(h1, h1);

        // FC: 10 independent accumulator updates (smem broadcast weights).
        const ulonglong2* fr0 = reinterpret_cast<const ulonglong2*>(&s_fck[j0][0]);
        const ulonglong2* fr1 = reinterpret_cast<const ulonglong2*>(&s_fck[j1][0]);
        ulonglong2 fA = fr0[0], fB = fr0[1];
        ulonglong2 fC = fr1[0], fD = fr1[1];
        u64 fE = s_fck[j0][4], fF = s_fck[j1][4];
        oa[0] = ffma2(fA.x, hp0, oa[0]);
        oa[1] = ffma2(fA.y, hp0, oa[1]);
        oa[2] = ffma2(fB.x, hp0, oa[2]);
        oa[3] = ffma2(fB.y, hp0, oa[3]);
        oa[4] = ffma2(fE,   hp0, oa[4]);
        oa[0] = ffma2(fC.x, hp1, oa[0]);
        oa[1] = ffma2(fC.y, hp1, oa[1]);
        oa[2] = ffma2(fD.x, hp1, oa[2]);
        oa[3] = ffma2(fD.y, hp1, oa[3]);
        oa[4] = ffma2(fF,   hp1, oa[4]);
    }
}

__global__ void __launch_bounds__(TPB, 7)
rnn_fused_kernel(const float* __restrict__ x,
                 const float* __restrict__ w_ih,
                 const float* __restrict__ b_ih,
                 const float* __restrict__ b_hh,
                 const float* __restrict__ fc_w,
                 const float* __restrict__ fc_b,
                 float* __restrict__ out)
{
    // Odd-j layer-1 weight rows: [k][p] = {w[2k+1][2p], w[2k+1][2p+1]}, 128B rows.
    __shared__ u64 s_wodd[NHID / 2][16];
    // FC weights: [j][q<5] = {fc_w[2q][j], fc_w[2q+1][j]}.
    __shared__ u64 s_fck[NHID][6];
    __shared__ u64 s_bp[NHID];          // {b_ih[j]+b_hh[j], 0}
    __shared__ u64 s_fcb[NOUT / 2];
    // Half-0 partials: [component][row_local]; 8B lane stride -> conflict-free.
    __shared__ u64 s_part[NOUT / 2][64];

    const int tid = threadIdx.x;

    for (int i = tid; i < (NHID / 2) * (NIN / 2); i += TPB) {
        int k = i / (NIN / 2), p = i % (NIN / 2);
        const float* wr = w_ih + (2 * k + 1) * NIN;
        s_wodd[k][p] = pk2(wr[2 * p], wr[2 * p + 1]);
    }
    for (int i = tid; i < NHID * (NOUT / 2); i += TPB) {
        int j = i / (NOUT / 2), q = i % (NOUT / 2);
        s_fck[j][q] = pk2(fc_w[(2 * q) * NHID + j], fc_w[(2 * q + 1) * NHID + j]);
    }
    for (int i = tid; i < NHID; i += TPB) {
        s_fck[i][5] = 0ull;
        s_bp[i] = pk2(b_ih[i] + b_hh[i], 0.0f);
    }
    if (tid < NOUT / 2) s_fcb[tid] = pk2(fc_b[2 * tid], fc_b[2 * tid + 1]);
    __syncthreads();

    const int wid  = tid >> 5;
    const int lane = tid & 31;
    const int half = wid & 1;                    // which 32 hidden units
    const int rloc = ((wid >> 1) << 5) + lane;   // row within CTA (0..63)
    const int row  = (blockIdx.x << 6) + rloc;

    // Last 28 floats of this row; float offset 756 is 16B aligned.
    u64 in[NIN / 2];
    {
        const float4* p = reinterpret_cast<const float4*>(x + (size_t)row * 784 + 756);
#pragma unroll
        for (int q = 0; q < 7; q++) {
            float4 v = p[q];
            in[2 * q]     = pk2(v.x, v.y);
            in[2 * q + 1] = pk2(v.z, v.w);
        }
    }

    u64 oa[NOUT / 2];
#pragma unroll
    for (int q = 0; q < NOUT / 2; q++) oa[q] = 0ull;

    // Warp-uniform branch: each instantiation has immediate const addresses.
    if (half == 0) half_work<0>(in, s_bp, s_wodd, s_fck, oa);
    else           half_work<32>(in, s_bp, s_wodd, s_fck, oa);

    // Half 0 publishes partials; half 1 combines (+ fc bias) and stores.
    if (half == 0) {
#pragma unroll
        for (int q = 0; q < NOUT / 2; q++) s_part[q][rloc] = oa[q];
    }
    __syncthreads();
    if (half == 1) {
        float2* o2 = reinterpret_cast<float2*>(out + (size_t)row * NOUT);
#pragma unroll
        for (int q = 0; q < NOUT / 2; q++) {
            u64 v = fadd2(fadd2(oa[q], s_part[q][rloc]), s_fcb[q]);
            float a, b;
            upk2(v, a, b);
            o2[q] = make_float2(a, b);
        }
    }
}

extern "C" void kernel_launch(void* const* d_in, const int* in_sizes, int n_in,
                              void* d_out, int out_size)
{
    (void)in_sizes; (void)n_in; (void)out_size;
    const float* x    = (const float*)d_in[0];
    const float* w_ih = (const float*)d_in[1];
    // d_in[2] = w_hh : unused (hx == 0)
    const float* b_ih = (const float*)d_in[3];
    const float* b_hh = (const float*)d_in[4];
    const float* fc_w = (const float*)d_in[5];
    const float* fc_b = (const float*)d_in[6];
    float* out = (float*)d_out;

    // Single staging memcpy: w_ih -> constant (even-j LDCU path). Async D2D,
    // graph-capturable, alloc-free, ordered before the kernel.
    cudaMemcpyToSymbolAsync(c_w64, d_in[1], NHID * NIN * sizeof(float), 0,
                            cudaMemcpyDeviceToDevice, 0);

    const int blocks = NB / 64;   // 1024, exact
    rnn_fused_kernel<<<blocks, TPB>>>(x, w_ih, b_ih, b_hh, fc_w, fc_b, out);
}

// round 15
// speedup vs baseline: 1.0152x; 1.0152x over previous
#include <cuda_runtime.h>
#include <cstdint>
#include <cstddef>

// RNN_49297634623576: out = fc_w @ tanh(w_ih @ x[:,27,:] + b_ih + b_hh) + fc_b
// hx == 0 => w_hh unused.
//
// R15 law (fits R1-R14): with ~28 warps/SM resident, issue pins at ~40% and
// duration tracks total instruction count; warps/SM capped ~29 by the reg
// file (70 regs). Levers: fewer instrs + fewer regs.
//  - Algebra: pre-scale inputs/biases by 2log2e (kills per-j FMUL); fold
//    tanh's 1-2r into FC: fc weights pre-scaled by -2, row-sums folded into
//    the output bias (kills per-j FFMA). tanh body 5 -> 3 instrs.
//  - __launch_bounds__(128, 8): target 64 regs -> 32 warps/SM (+14%).
// Base otherwise = R13 (LDCU layer-1 full-unroll, warp-split halves,
// 1024 CTAs, single memcpy graph node).

#define NB   65536
#define NIN  28
#define NHID 64
#define NOUT 10
#define TPB  128   // 4 warps: (half, rowgroup); 64 rows/CTA -> 1024 CTAs

typedef unsigned long long u64;

__constant__ u64 c_w64[NHID * NIN / 2];  // raw w_ih: [j][p] = {w[j][2p], w[j][2p+1]}

__device__ __forceinline__ u64 pk2(float a, float b) {
    u64 r; asm("mov.b64 %0,{%1,%2};" : "=l"(r) : "f"(a), "f"(b)); return r;
}
__device__ __forceinline__ void upk2(u64 v, float& a, float& b) {
    asm("mov.b64 {%0,%1},%2;" : "=f"(a), "=f"(b) : "l"(v));
}
__device__ __forceinline__ u64 ffma2(u64 a, u64 b, u64 c) {
    u64 d; asm("fma.rn.f32x2 %0,%1,%2,%3;" : "=l"(d) : "l"(a), "l"(b), "l"(c)); return d;
}
__device__ __forceinline__ u64 fmul2(u64 a, u64 b) {
    u64 d; asm("mul.rn.f32x2 %0,%1,%2;" : "=l"(d) : "l"(a), "l"(b)); return d;
}
__device__ __forceinline__ u64 fadd2(u64 a, u64 b) {
    u64 d; asm("add.rn.f32x2 %0,%1,%2;" : "=l"(d) : "l"(a), "l"(b)); return d;
}
__device__ __forceinline__ float hsum2(u64 v) {
    float a, b; upk2(v, a, b); return a + b;
}

// r(A) = rcp(exp2(A) + 1), where A = 2*log2(e)*a is pre-scaled upstream.
// tanh(a) = 1 - 2*r; the 1 and -2 are folded into the FC layer.
__device__ __forceinline__ float sig_r(float A) {
    float e, r;
    asm("ex2.approx.ftz.f32 %0, %1;" : "=f"(e) : "f"(A));
    asm("rcp.approx.ftz.f32 %0, %1;" : "=f"(r) : "f"(e + 1.0f));
    return r;
}

// One half's work: 32 hidden units [JBASE, JBASE+32), 2 j per iteration.
// Fully unrolled: every c_w64 access is an immediate -> uniform-port LDCU.
template <int JBASE>
__device__ __forceinline__ void half_work(const u64 (&in)[NIN / 2],
                                          const u64* s_bp,
                                          const u64 (*s_fck)[6],
                                          u64 (&oa)[NOUT / 2])
{
#pragma unroll
    for (int jj = 0; jj < 32; jj += 2) {
        const int j0 = JBASE + jj, j1 = j0 + 1;

        // Two independent layer-1 chains; accumulators are pre-scaled by
        // 2log2e (inputs and biases both carry the factor).
        u64 a0 = s_bp[j0];
        u64 a1 = s_bp[j1];
#pragma unroll
        for (int p = 0; p < NIN / 2; p++) {
            a0 = ffma2(c_w64[j0 * (NIN / 2) + p], in[p], a0);
            a1 = ffma2(c_w64[j1 * (NIN / 2) + p], in[p], a1);
        }

        // 3-instr activation core (ex2, add+rcp) per j; 1-2r folded into FC.
        float r0 = sig_r(hsum2(a0));
        float r1 = sig_r(hsum2(a1));
        u64 hp0 = pk2(r0, r0);
        u64 hp1 = pk2(r1, r1);

        // FC: weights pre-scaled by -2; 10 independent accumulator updates.
        const ulonglong2* fr0 = reinterpret_cast<const ulonglong2*>(&s_fck[j0][0]);
        const ulonglong2* fr1 = reinterpret_cast<const ulonglong2*>(&s_fck[j1][0]);
        ulonglong2 fA = fr0[0], fB = fr0[1];
        ulonglong2 fC = fr1[0], fD = fr1[1];
        u64 fE = s_fck[j0][4], fF = s_fck[j1][4];
        oa[0] = ffma2(fA.x, hp0, oa[0]);
        oa[1] = ffma2(fA.y, hp0, oa[1]);
        oa[2] = ffma2(fB.x, hp0, oa[2]);
        oa[3] = ffma2(fB.y, hp0, oa[3]);
        oa[4] = ffma2(fE,   hp0, oa[4]);
        oa[0] = ffma2(fC.x, hp1, oa[0]);
        oa[1] = ffma2(fC.y, hp1, oa[1]);
        oa[2] = ffma2(fD.x, hp1, oa[2]);
        oa[3] = ffma2(fD.y, hp1, oa[3]);
        oa[4] = ffma2(fF,   hp1, oa[4]);
    }
}

__global__ void __launch_bounds__(TPB, 8)
rnn_fused_kernel(const float* __restrict__ x,
                 const float* __restrict__ b_ih,
                 const float* __restrict__ b_hh,
                 const float* __restrict__ fc_w,
                 const float* __restrict__ fc_b,
                 float* __restrict__ out)
{
    // FC weights (pre-scaled by -2): [j][q<5] = {-2fc_w[2q][j], -2fc_w[2q+1][j]}.
    __shared__ u64 s_fck[NHID][6];
    __shared__ u64 s_bp[NHID];          // {2log2e*(b_ih[j]+b_hh[j]), 0}
    __shared__ u64 s_fcb[NOUT / 2];     // {fc_b[k] + sum_j fc_w[k][j], ...}
    __shared__ float s_tmp[NOUT];
    // Half-0 partials: [component][row_local]; 8B lane stride -> conflict-free.
    __shared__ u64 s_part[NOUT / 2][64];

    const int tid = threadIdx.x;
    const float TWO_LOG2E = 2.8853900817779268f;

    for (int i = tid; i < NHID * (NOUT / 2); i += TPB) {
        int j = i / (NOUT / 2), q = i % (NOUT / 2);
        s_fck[j][q] = pk2(-2.0f * fc_w[(2 * q) * NHID + j],
                          -2.0f * fc_w[(2 * q + 1) * NHID + j]);
    }
    for (int i = tid; i < NHID; i += TPB) {
        s_fck[i][5] = 0ull;
        s_bp[i] = pk2(TWO_LOG2E * (b_ih[i] + b_hh[i]), 0.0f);
    }
    if (tid < NOUT) {
        float s = fc_b[tid];
        for (int j = 0; j < NHID; j++) s += fc_w[tid * NHID + j];
        s_tmp[tid] = s;
    }
    __syncthreads();
    if (tid < NOUT / 2) s_fcb[tid] = pk2(s_tmp[2 * tid], s_tmp[2 * tid + 1]);
    __syncthreads();

    const int wid  = tid >> 5;
    const int lane = tid & 31;
    const int half = wid & 1;                    // which 32 hidden units
    const int rloc = ((wid >> 1) << 5) + lane;   // row within CTA (0..63)
    const int row  = (blockIdx.x << 6) + rloc;

    // Last 28 floats of this row, PRE-SCALED by 2log2e (float offset 756 is
    // 16B aligned).
    u64 in[NIN / 2];
    {
        const u64 Cpk = pk2(TWO_LOG2E, TWO_LOG2E);
        const float4* p = reinterpret_cast<const float4*>(x + (size_t)row * 784 + 756);
#pragma unroll
        for (int q = 0; q < 7; q++) {
            float4 v = p[q];
            in[2 * q]     = fmul2(pk2(v.x, v.y), Cpk);
            in[2 * q + 1] = fmul2(pk2(v.z, v.w), Cpk);
        }
    }

    u64 oa[NOUT / 2];
#pragma unroll
    for (int q = 0; q < NOUT / 2; q++) oa[q] = 0ull;

    // Warp-uniform branch: each instantiation has immediate const addresses.
    if (half == 0) half_work<0>(in, s_bp, s_fck, oa);
    else           half_work<32>(in, s_bp, s_fck, oa);

    // Half 0 publishes partials; half 1 combines (+ folded bias) and stores.
    if (half == 0) {
#pragma unroll
        for (int q = 0; q < NOUT / 2; q++) s_part[q][rloc] = oa[q];
    }
    __syncthreads();
    if (half == 1) {
        float2* o2 = reinterpret_cast<float2*>(out + (size_t)row * NOUT);
#pragma unroll
        for (int q = 0; q < NOUT / 2; q++) {
            u64 v = fadd2(fadd2(oa[q], s_part[q][rloc]), s_fcb[q]);
            float a, b;
            upk2(v, a, b);
            o2[q] = make_float2(a, b);
        }
    }
}

extern "C" void kernel_launch(void* const* d_in, const int* in_sizes, int n_in,
                              void* d_out, int out_size)
{
    (void)in_sizes; (void)n_in; (void)out_size;
    const float* x    = (const float*)d_in[0];
    // d_in[2] = w_hh : unused (hx == 0)
    const float* b_ih = (const float*)d_in[3];
    const float* b_hh = (const float*)d_in[4];
    const float* fc_w = (const float*)d_in[5];
    const float* fc_b = (const float*)d_in[6];
    float* out = (float*)d_out;

    // Single staging memcpy: w_ih -> constant (LDCU path). Async D2D,
    // graph-capturable, alloc-free, ordered before the kernel.
    cudaMemcpyToSymbolAsync(c_w64, d_in[1], NHID * NIN * sizeof(float), 0,
                            cudaMemcpyDeviceToDevice, 0);

    const int blocks = NB / 64;   // 1024, exact
    rnn_fused_kernel<<<blocks, TPB>>>(x, b_ih, b_hh, fc_w, fc_b, out);
}

// round 17
// speedup vs baseline: 1.1215x; 1.1047x over previous
#include <cuda_runtime.h>
#include <cuda_bf16.h>
#include <mma.h>
#include <cstdint>
#include <cstddef>

// RNN_49297634623576: out = fc_w @ tanh(w_ih @ x[:,27,:] + b_ih + b_hh) + fc_b
// hx == 0 => w_hh unused.
//
// R17: tcgen05 PTX is rejected (harness compiles via compute_103, no 'a'
// features). Use the portable tensor path instead: wmma bf16 (HMMA).
//   A[128x96 bf16] = [xh | xh | xl], B[64x96] = [wh | wl | wh]  (K-concat
//   encodes xh*wh + xh*wl + xl*wh in ONE GEMM; lo*lo term ~1e-7, dropped).
//   4 warps x (2 Mtiles x 4 Ntiles x 6 Ksteps) wmma 16x16x16 -> D f32.
//   D[128x68] f32 stored to smem (union over A/B), then the R15 folded
//   scalar epilogue (2log2e pre-scale, 3-instr sig_r, -2-folded FC).
// ~2.05M total warp-issues vs R13's 6.35M. No __constant__, no extra nodes.

#define NB   65536
#define NIN  28
#define NHID 64
#define NOUT 10
#define TPB  128            // 128 rows/CTA -> 512 CTAs

#define LDT  104            // tile leading dim (elements); 208B rows, ldmatrix conflict-free
#define LDD  68             // D leading dim (floats); 272B rows, 16B aligned
#define A_BYTES (128 * LDT * 2)          // 26624
#define B_BYTES (NHID * LDT * 2)         // 13312
#define BUF_BYTES (A_BYTES + B_BYTES)    // 39936; D needs 128*68*4=34816 <= this

typedef unsigned long long u64;
using namespace nvcuda;

__device__ __forceinline__ u64 pk2(float a, float b) {
    u64 r; asm("mov.b64 %0,{%1,%2};" : "=l"(r) : "f"(a), "f"(b)); return r;
}
__device__ __forceinline__ void upk2(u64 v, float& a, float& b) {
    asm("mov.b64 {%0,%1},%2;" : "=f"(a), "=f"(b) : "l"(v));
}
__device__ __forceinline__ u64 ffma2(u64 a, u64 b, u64 c) {
    u64 d; asm("fma.rn.f32x2 %0,%1,%2,%3;" : "=l"(d) : "l"(a), "l"(b), "l"(c)); return d;
}
__device__ __forceinline__ u64 fadd2(u64 a, u64 b) {
    u64 d; asm("add.rn.f32x2 %0,%1,%2;" : "=l"(d) : "l"(a), "l"(b)); return d;
}
// r = rcp(exp2(A)+1); tanh folded into FC as out = fcb' - 2*fcw*r.
__device__ __forceinline__ float sig_r(float A) {
    float e, r;
    asm("ex2.approx.ftz.f32 %0, %1;" : "=f"(e) : "f"(A));
    asm("rcp.approx.ftz.f32 %0, %1;" : "=f"(r) : "f"(e + 1.0f));
    return r;
}
__device__ __forceinline__ uint32_t pack_bf2(__nv_bfloat16 a, __nv_bfloat16 b) {
    return (uint32_t)__bfloat16_as_ushort(a) |
           ((uint32_t)__bfloat16_as_ushort(b) << 16);
}

__global__ void __launch_bounds__(TPB)
rnn_wmma_kernel(const float* __restrict__ x,
                const float* __restrict__ w_ih,
                const float* __restrict__ b_ih,
                const float* __restrict__ b_hh,
                const float* __restrict__ fc_w,
                const float* __restrict__ fc_b,
                float* __restrict__ out)
{
    // Union buffer: A/B bf16 tiles during GEMM, D f32 after.
    __shared__ alignas(128) unsigned char s_buf[BUF_BYTES];
    __shared__ u64 s_fck[NHID][6];     // {-2fc_w[2q][j], -2fc_w[2q+1][j]}
    __shared__ u64 s_bpp[NHID / 2];    // {C*(bih+bhh)[2q], C*(bih+bhh)[2q+1]}
    __shared__ u64 s_fcb[NOUT / 2];    // folded output bias pairs
    __shared__ float s_tmp[NOUT];

    __nv_bfloat16* At = reinterpret_cast<__nv_bfloat16*>(s_buf);
    __nv_bfloat16* Bt = reinterpret_cast<__nv_bfloat16*>(s_buf + A_BYTES);
    float*         Dt = reinterpret_cast<float*>(s_buf);

    const int tid  = threadIdx.x;
    const int wid  = tid >> 5;
    const float C = 2.8853900817779268f;   // 2*log2(e)

    // ---- Phase 0: zero tiles (padding must be 0 for the GEMM) ----
    {
        uint4 z = make_uint4(0, 0, 0, 0);
        uint4* pb = reinterpret_cast<uint4*>(s_buf);
        for (int i = tid; i < BUF_BYTES / 16; i += TPB) pb[i] = z;
    }
    __syncthreads();

    // ---- Phase 1: fill tiles + epilogue tables ----
    const int rbase = blockIdx.x * 128;
    const int row   = rbase + tid;

    // A row (this thread's x row): [xh(28) 0x4 | xh(28) 0x4 | xl(28) 0x4].
    {
        const float4* px = reinterpret_cast<const float4*>(x + (size_t)row * 784 + 756);
        float v[NIN];
#pragma unroll
        for (int q = 0; q < 7; q++) {
            float4 t = px[q];
            v[4*q] = t.x; v[4*q+1] = t.y; v[4*q+2] = t.z; v[4*q+3] = t.w;
        }
        uint32_t* ar = reinterpret_cast<uint32_t*>(At + tid * LDT);
#pragma unroll
        for (int k = 0; k < NIN; k += 2) {
            __nv_bfloat16 h0 = __float2bfloat16_rn(v[k]);
            __nv_bfloat16 h1 = __float2bfloat16_rn(v[k+1]);
            __nv_bfloat16 l0 = __float2bfloat16_rn(v[k]   - __bfloat162float(h0));
            __nv_bfloat16 l1 = __float2bfloat16_rn(v[k+1] - __bfloat162float(h1));
            uint32_t hp = pack_bf2(h0, h1), lp = pack_bf2(l0, l1);
            ar[k / 2]            = hp;   // seg0: xh
            ar[(32 + k) / 2]     = hp;   // seg1: xh
            ar[(64 + k) / 2]     = lp;   // seg2: xl
        }
    }
    // B row n = tid (<64): [wh | wl | wh].
    if (tid < NHID) {
        const float4* pw = reinterpret_cast<const float4*>(w_ih + tid * NIN);
        float v[NIN];
#pragma unroll
        for (int q = 0; q < 7; q++) {
            float4 t = pw[q];
            v[4*q] = t.x; v[4*q+1] = t.y; v[4*q+2] = t.z; v[4*q+3] = t.w;
        }
        uint32_t* br = reinterpret_cast<uint32_t*>(Bt + tid * LDT);
#pragma unroll
        for (int k = 0; k < NIN; k += 2) {
            __nv_bfloat16 h0 = __float2bfloat16_rn(v[k]);
            __nv_bfloat16 h1 = __float2bfloat16_rn(v[k+1]);
            __nv_bfloat16 l0 = __float2bfloat16_rn(v[k]   - __bfloat162float(h0));
            __nv_bfloat16 l1 = __float2bfloat16_rn(v[k+1] - __bfloat162float(h1));
            uint32_t hp = pack_bf2(h0, h1), lp = pack_bf2(l0, l1);
            br[k / 2]            = hp;   // seg0: wh
            br[(32 + k) / 2]     = lp;   // seg1: wl
            br[(64 + k) / 2]     = hp;   // seg2: wh
        }
    }
    // Epilogue tables.
    for (int i = tid; i < NHID * (NOUT / 2); i += TPB) {
        int j = i / (NOUT / 2), q = i % (NOUT / 2);
        s_fck[j][q] = pk2(-2.0f * fc_w[(2 * q) * NHID + j],
                          -2.0f * fc_w[(2 * q + 1) * NHID + j]);
    }
    for (int i = tid; i < NHID / 2; i += TPB) {
        s_bpp[i] = pk2(C * (b_ih[2 * i] + b_hh[2 * i]),
                       C * (b_ih[2 * i + 1] + b_hh[2 * i + 1]));
    }
    if (tid < NOUT) {
        float s = fc_b[tid];
        for (int j = 0; j < NHID; j++) s += fc_w[tid * NHID + j];
        s_tmp[tid] = s;
    }
    __syncthreads();

    if (tid < NOUT / 2) s_fcb[tid] = pk2(s_tmp[2 * tid], s_tmp[2 * tid + 1]);

    // ---- Phase 2: GEMM. Warp w owns rows [32w, 32w+32) x all 64 cols ----
    wmma::fragment<wmma::accumulator, 16, 16, 16, float> acc[2][4];
#pragma unroll
    for (int mt = 0; mt < 2; mt++)
#pragma unroll
        for (int nt = 0; nt < 4; nt++) wmma::fill_fragment(acc[mt][nt], 0.0f);

#pragma unroll
    for (int ks = 0; ks < 6; ks++) {
        wmma::fragment<wmma::matrix_a, 16, 16, 16, __nv_bfloat16, wmma::row_major> af[2];
        wmma::fragment<wmma::matrix_b, 16, 16, 16, __nv_bfloat16, wmma::col_major> bf[4];
#pragma unroll
        for (int mt = 0; mt < 2; mt++)
            wmma::load_matrix_sync(af[mt], At + (wid * 32 + mt * 16) * LDT + ks * 16, LDT);
#pragma unroll
        for (int nt = 0; nt < 4; nt++)
            wmma::load_matrix_sync(bf[nt], Bt + (nt * 16) * LDT + ks * 16, LDT);
#pragma unroll
        for (int mt = 0; mt < 2; mt++)
#pragma unroll
            for (int nt = 0; nt < 4; nt++)
                wmma::mma_sync(acc[mt][nt], af[mt], bf[nt], acc[mt][nt]);
    }
    __syncthreads();   // all warps done reading A/B before D overwrites them

    // ---- Phase 3: D -> smem (union), then scalar folded epilogue ----
#pragma unroll
    for (int mt = 0; mt < 2; mt++)
#pragma unroll
        for (int nt = 0; nt < 4; nt++)
            wmma::store_matrix_sync(Dt + (wid * 32 + mt * 16) * LDD + nt * 16,
                                    acc[mt][nt], LDD, wmma::mem_row_major);
    __syncthreads();

    // Thread owns row tid: read 64 f32 pre-activations, apply folded algebra.
    float dv[NHID];
    {
        const float4* dr = reinterpret_cast<const float4*>(Dt + tid * LDD);
#pragma unroll
        for (int q = 0; q < NHID / 4; q++) {
            float4 t = dr[q];
            dv[4*q] = t.x; dv[4*q+1] = t.y; dv[4*q+2] = t.z; dv[4*q+3] = t.w;
        }
    }

    const u64 Cpk = pk2(C, C);
    u64 oa[NOUT / 2];
#pragma unroll
    for (int q = 0; q < NOUT / 2; q++) oa[q] = 0ull;

#pragma unroll
    for (int q = 0; q < NHID / 2; q++) {
        u64 Dp = pk2(dv[2 * q], dv[2 * q + 1]);
        u64 A2 = ffma2(Dp, Cpk, s_bpp[q]);     // pre-scaled activation pair
        float A0, A1;
        upk2(A2, A0, A1);
        float r0 = sig_r(A0);
        float r1 = sig_r(A1);
        u64 hp0 = pk2(r0, r0);
        u64 hp1 = pk2(r1, r1);
        const int j0 = 2 * q, j1 = j0 + 1;
        const ulonglong2* f0 = reinterpret_cast<const ulonglong2*>(&s_fck[j0][0]);
        const ulonglong2* f1 = reinterpret_cast<const ulonglong2*>(&s_fck[j1][0]);
        ulonglong2 fA = f0[0], fB = f0[1];
        ulonglong2 fC = f1[0], fD = f1[1];
        u64 fE = s_fck[j0][4], fF = s_fck[j1][4];
        oa[0] = ffma2(fA.x, hp0, oa[0]);
        oa[1] = ffma2(fA.y, hp0, oa[1]);
        oa[2] = ffma2(fB.x, hp0, oa[2]);
        oa[3] = ffma2(fB.y, hp0, oa[3]);
        oa[4] = ffma2(fE,   hp0, oa[4]);
        oa[0] = ffma2(fC.x, hp1, oa[0]);
        oa[1] = ffma2(fC.y, hp1, oa[1]);
        oa[2] = ffma2(fD.x, hp1, oa[2]);
        oa[3] = ffma2(fD.y, hp1, oa[3]);
        oa[4] = ffma2(fF,   hp1, oa[4]);
    }

    // Store 10 floats (5x STG.64); 40B row stride -> 8B aligned.
    {
        float2* o2 = reinterpret_cast<float2*>(out + (size_t)row * NOUT);
#pragma unroll
        for (int q = 0; q < NOUT / 2; q++) {
            u64 v = fadd2(oa[q], s_fcb[q]);
            float a, b;
            upk2(v, a, b);
            o2[q] = make_float2(a, b);
        }
    }
}

extern "C" void kernel_launch(void* const* d_in, const int* in_sizes, int n_in,
                              void* d_out, int out_size)
{
    (void)in_sizes; (void)n_in; (void)out_size;
    const float* x    = (const float*)d_in[0];
    const float* w_ih = (const float*)d_in[1];
    // d_in[2] = w_hh : unused (hx == 0)
    const float* b_ih = (const float*)d_in[3];
    const float* b_hh = (const float*)d_in[4];
    const float* fc_w = (const float*)d_in[5];
    const float* fc_b = (const float*)d_in[6];
    float* out = (float*)d_out;

    const int blocks = NB / 128;   // 512, exact
    rnn_wmma_kernel<<<blocks, TPB>>>(x, w_ih, b_ih, b_hh, fc_w, fc_b, out);
}